// round 15
// baseline (speedup 1.0000x reference)
#include <cuda_runtime.h>
#include <cuda_bf16.h>
#include <cstdint>
#include <math.h>

#define N_SAMP 2048
#define DD 784
#define KR 10
#define LAYERS 32
#define KCLS 10
#define HCONST 0.001f

__device__ float g_s2[2 * N_SAMP * 100];            // ping-pong s buffers
__device__ float g_shist[33 * N_SAMP * 100];
__device__ __nv_bfloat16 g_xh[N_SAMP * DD];
__device__ __nv_bfloat16 g_zh2[2 * N_SAMP * DD];    // ping-pong dY buffers
__device__ __nv_bfloat16 g_wh[33 * DD * DD];
__device__ __nv_bfloat16 g_uvhh[N_SAMP * 560];

// ---------------- weights -> bf16 -------------------------------------------
__global__ void wcvt_kernel(const float* __restrict__ W0, const float* __restrict__ Ws) {
    size_t idx = ((size_t)blockIdx.x * blockDim.x + threadIdx.x) * 4;
    size_t total = (size_t)33 * DD * DD;
    if (idx >= total) return;
    size_t per = (size_t)DD * DD;
    const float* src = (idx < per) ? (W0 + idx) : (Ws + (idx - per));
    float4 v = *(const float4*)src;
    __nv_bfloat16 o[4] = {__float2bfloat16(v.x), __float2bfloat16(v.y),
                          __float2bfloat16(v.z), __float2bfloat16(v.w)};
    *(uint2*)(g_wh + idx) = *(uint2*)o;
}

// ---------------- init -------------------------------------------------------
__global__ void init_kernel(const float* __restrict__ X) {
    __shared__ float u[280], vh[280], s[100], US[280];
    int i = blockIdx.x, t = threadIdx.x;
    const float* xb = X + (size_t)i * 840;
    for (int k = t; k < 280; k += blockDim.x) {
        float uu = xb[k], vv = xb[560 + k];
        u[k] = uu; vh[k] = vv;
        g_uvhh[(size_t)i * 560 + k] = __float2bfloat16(uu);
        g_uvhh[(size_t)i * 560 + 280 + k] = __float2bfloat16(vv);
    }
    for (int k = t; k < 100; k += blockDim.x) { float v = xb[280 + k]; s[k] = v; g_s2[i * 100 + k] = v; }
    __syncthreads();
    for (int k = t; k < 280; k += blockDim.x) {
        int r = k / 10, b = k % 10;
        float acc = 0.f;
#pragma unroll
        for (int a = 0; a < 10; a++) acc += u[r * 10 + a] * s[a * 10 + b];
        US[k] = acc;
    }
    __syncthreads();
    for (int k = t; k < DD; k += blockDim.x) {
        int r = k / 28, c = k % 28;
        float acc = 0.f;
#pragma unroll
        for (int b = 0; b < 10; b++) acc += US[r * 10 + b] * vh[b * 28 + c];
        g_xh[(size_t)i * DD + k] = __float2bfloat16(acc);
    }
}

// ============ fused layer: phase A = update(col-1) (block-local), ============
// ============ phase B = gemm zh[col] = relu(x @ W^T + b)          ============
#define GBM 128
#define GBN 112
#define GBK 64
#define SPAD 72
#define NIT 13
#define ASB (2 * GBM * SPAD * 2)     // 36864
#define BSB (2 * GBN * SPAD * 2)     // 32256
#define GEMM_SMEM (ASB + BSB)        // 69120

__device__ __forceinline__ unsigned smem_u32(const void* p) {
    return (unsigned)__cvta_generic_to_shared(p);
}
__device__ __forceinline__ void cp16(unsigned dst, const void* src, int sz) {
    asm volatile("cp.async.cg.shared.global [%0], [%1], 16, %2;\n"
                 :: "r"(dst), "l"(src), "r"(sz));
}

__global__ __launch_bounds__(256) void layer_kernel(const __nv_bfloat16* __restrict__ W,
                                                    const float* __restrict__ bias,
                                                    int do_relu, int col) {
    extern __shared__ char dsm[];
    __nv_bfloat16 (*As)[GBM][SPAD] = (__nv_bfloat16(*)[GBM][SPAD])dsm;
    __nv_bfloat16 (*Bs)[GBN][SPAD] = (__nv_bfloat16(*)[GBN][SPAD])(dsm + ASB);

    int bm = blockIdx.y * GBM;
    int bn = blockIdx.x * GBN;
    int tid = threadIdx.x;
    int wid = tid >> 5, lane = tid & 31;
    int wm = wid & 3, wn = wid >> 2;
    int g = lane >> 2, tg = lane & 3;

    // ================= phase A: update(col-1) for samples [bm, bm+128) ======
    if (col > 0) {
        int uc = col - 1;
        const float* srd = g_s2 + (size_t)(uc & 1) * N_SAMP * 100;
        float* swr = g_s2 + (size_t)((uc + 1) & 1) * N_SAMP * 100;
        const __nv_bfloat16* zbase = g_zh2 + (size_t)(uc & 1) * N_SAMP * DD;
        // per-warp scratch: 2008 floats
        float* wsc = (float*)dsm + wid * 2008;
        float* u  = wsc;
        float* vh = u + 280;
        float* P  = vh + 280;
        float* US = P + 280;
        float* sv = US + 280;
        float* z  = sv + 104;          // 784

        for (int n = 0; n < 16; n++) {
            int i = bm + wid * 16 + n;
            const __nv_bfloat162* uvp = (const __nv_bfloat162*)(g_uvhh + (size_t)i * 560);
            for (int k = lane; k < 280; k += 32) {
                float2 p = __bfloat1622float2(uvp[k]);
                if (k < 140) { u[2 * k] = p.x; u[2 * k + 1] = p.y; }
                else { int k2 = k - 140; vh[2 * k2] = p.x; vh[2 * k2 + 1] = p.y; }
            }
            const __nv_bfloat162* zp = (const __nv_bfloat162*)(zbase + (size_t)i * DD);
            for (int k = lane; k < 392; k += 32) {
                float2 v = __bfloat1622float2(zp[k]);
                z[2 * k] = v.x; z[2 * k + 1] = v.y;
            }
            for (int k = lane; k < 100; k += 32) sv[k] = srd[(size_t)i * 100 + k];
            __syncwarp();
            for (int k = lane; k < 280; k += 32) {
                int a = k / 28, c = k % 28;
                float acc = 0.f;
#pragma unroll
                for (int r = 0; r < 28; r++) acc += u[r * 10 + a] * z[r * 28 + c];
                P[k] = acc;
            }
            __syncwarp();
            for (int k = lane; k < 100; k += 32) {
                int a = k / 10, b = k % 10;
                float acc = 0.f;
#pragma unroll
                for (int c = 0; c < 28; c++) acc += P[a * 28 + c] * vh[b * 28 + c];
                float sn = sv[k] + HCONST * acc;
                sv[k] = sn;
                swr[(size_t)i * 100 + k] = sn;
                g_shist[(size_t)uc * N_SAMP * 100 + (size_t)i * 100 + k] = sn;
            }
            __syncwarp();
            for (int k = lane; k < 280; k += 32) {
                int r = k / 10, b = k % 10;
                float acc = 0.f;
#pragma unroll
                for (int a = 0; a < 10; a++) acc += u[r * 10 + a] * sv[a * 10 + b];
                US[k] = acc;
            }
            __syncwarp();
            __nv_bfloat162* xd = (__nv_bfloat162*)(g_xh + (size_t)i * DD);
            for (int p = lane; p < 392; p += 32) {
                int r = p / 14, cc = (p % 14) * 2;
                float a0 = 0.f, a1 = 0.f;
#pragma unroll
                for (int b = 0; b < 10; b++) {
                    float us = US[r * 10 + b];
                    a0 += us * vh[b * 28 + cc];
                    a1 += us * vh[b * 28 + cc + 1];
                }
                xd[p] = __float22bfloat162_rn(make_float2(a0, a1));
            }
            __syncwarp();
        }
        __syncthreads();   // all x writes visible before gemm A loads
    }

    // ================= phase B: gemm (R13 mainloop) ==========================
    __nv_bfloat16* zout = g_zh2 + (size_t)(col & 1) * N_SAMP * DD;
    float acc[2][7][4] = {};

    auto load_stage = [&](int it, int buf) {
        int k0 = it * GBK;
#pragma unroll
        for (int ii = 0; ii < 4; ii++) {
            int task = tid + ii * 256;
            int row = task >> 3, cg = task & 7;
            int kk = k0 + 8 * cg;
            const __nv_bfloat16* src = g_xh + (size_t)(bm + row) * DD + kk;
            cp16(smem_u32(&As[buf][row][8 * cg]), src, (kk < DD) ? 16 : 0);
        }
#pragma unroll
        for (int ii = 0; ii < 4; ii++) {
            int task = tid + ii * 256;
            if (task < 896) {
                int row = task >> 3, cg = task & 7;
                int kk = k0 + 8 * cg;
                const __nv_bfloat16* src = W + (size_t)(bn + row) * DD + kk;
                cp16(smem_u32(&Bs[buf][row][8 * cg]), src, (kk < DD) ? 16 : 0);
            }
        }
        asm volatile("cp.async.commit_group;\n");
    };

    load_stage(0, 0);
    for (int it = 0; it < NIT; it++) {
        int buf = it & 1;
        if (it + 1 < NIT) {
            load_stage(it + 1, buf ^ 1);
            asm volatile("cp.async.wait_group 1;\n");
        } else {
            asm volatile("cp.async.wait_group 0;\n");
        }
        __syncthreads();
#pragma unroll
        for (int kh = 0; kh < 4; kh++) {
            int kk = 16 * kh;
            unsigned a[2][4];
#pragma unroll
            for (int mi = 0; mi < 2; mi++) {
                int r0 = wm * 32 + mi * 16 + g;
                a[mi][0] = *(const unsigned*)&As[buf][r0][kk + 2 * tg];
                a[mi][1] = *(const unsigned*)&As[buf][r0 + 8][kk + 2 * tg];
                a[mi][2] = *(const unsigned*)&As[buf][r0][kk + 2 * tg + 8];
                a[mi][3] = *(const unsigned*)&As[buf][r0 + 8][kk + 2 * tg + 8];
            }
#pragma unroll
            for (int j = 0; j < 7; j++) {
                int nr = wn * 56 + j * 8 + g;
                unsigned b0 = *(const unsigned*)&Bs[buf][nr][kk + 2 * tg];
                unsigned b1 = *(const unsigned*)&Bs[buf][nr][kk + 2 * tg + 8];
#pragma unroll
                for (int mi = 0; mi < 2; mi++) {
                    asm volatile(
                        "mma.sync.aligned.m16n8k16.row.col.f32.bf16.bf16.f32 "
                        "{%0,%1,%2,%3}, {%4,%5,%6,%7}, {%8,%9}, {%0,%1,%2,%3};"
                        : "+f"(acc[mi][j][0]), "+f"(acc[mi][j][1]),
                          "+f"(acc[mi][j][2]), "+f"(acc[mi][j][3])
                        : "r"(a[mi][0]), "r"(a[mi][1]), "r"(a[mi][2]), "r"(a[mi][3]),
                          "r"(b0), "r"(b1));
                }
            }
        }
        __syncthreads();
    }
    // epilogue: bias + relu -> bf16 packed
#pragma unroll
    for (int mi = 0; mi < 2; mi++) {
        int row0 = bm + wm * 32 + mi * 16 + g;
        int row1 = row0 + 8;
#pragma unroll
        for (int j = 0; j < 7; j++) {
            int c2 = bn + wn * 56 + j * 8 + 2 * tg;
            float b0 = bias ? bias[c2] : 0.f;
            float b1 = bias ? bias[c2 + 1] : 0.f;
            float v00 = acc[mi][j][0] + b0, v01 = acc[mi][j][1] + b1;
            float v10 = acc[mi][j][2] + b0, v11 = acc[mi][j][3] + b1;
            if (do_relu) {
                v00 = fmaxf(v00, 0.f); v01 = fmaxf(v01, 0.f);
                v10 = fmaxf(v10, 0.f); v11 = fmaxf(v11, 0.f);
            }
            *(__nv_bfloat162*)(zout + (size_t)row0 * DD + c2) =
                __float22bfloat162_rn(make_float2(v00, v01));
            *(__nv_bfloat162*)(zout + (size_t)row1 * DD + c2) =
                __float22bfloat162_rn(make_float2(v10, v11));
        }
    }
}

// ---------------- final standalone update (col=32) ---------------------------
__global__ __launch_bounds__(256) void update_kernel(int col) {
    __shared__ float su[2][280], svh[2][280], sdY[2][784], sP[2][280], ss[2][104], sUS[2][280];
    int t = threadIdx.x;
    int w = t >> 7;
    int tl = t & 127;
    int i = blockIdx.x * 2 + w;
    const float* srd = g_s2 + (size_t)(col & 1) * N_SAMP * 100;
    float* swr = g_s2 + (size_t)((col + 1) & 1) * N_SAMP * 100;
    const __nv_bfloat16* zbase = g_zh2 + (size_t)(col & 1) * N_SAMP * DD;
    const __nv_bfloat162* uvp = (const __nv_bfloat162*)(g_uvhh + (size_t)i * 560);
#pragma unroll
    for (int it = 0; it < 3; it++) {
        int k = tl + 128 * it;
        if (k < 280) {
            float2 p = __bfloat1622float2(uvp[k]);
            if (k < 140) { su[w][2 * k] = p.x; su[w][2 * k + 1] = p.y; }
            else { int k2 = k - 140; svh[w][2 * k2] = p.x; svh[w][2 * k2 + 1] = p.y; }
        }
    }
    const __nv_bfloat162* zsrc = (const __nv_bfloat162*)(zbase + (size_t)i * DD);
#pragma unroll
    for (int it = 0; it < 4; it++) {
        int k = tl + 128 * it;
        if (k < 392) {
            float2 v = __bfloat1622float2(zsrc[k]);
            sdY[w][2 * k] = v.x; sdY[w][2 * k + 1] = v.y;
        }
    }
    if (tl < 100) ss[w][tl] = srd[(size_t)i * 100 + tl];
    __syncthreads();
#pragma unroll
    for (int it = 0; it < 3; it++) {
        int k = tl + 128 * it;
        if (k < 280) {
            int a = k / 28, c = k % 28;
            float acc = 0.f;
#pragma unroll
            for (int r = 0; r < 28; r++) acc += su[w][r * 10 + a] * sdY[w][r * 28 + c];
            sP[w][k] = acc;
        }
    }
    __syncthreads();
    if (tl < 100) {
        int a = tl / 10, b = tl % 10;
        float acc = 0.f;
#pragma unroll
        for (int c = 0; c < 28; c++) acc += sP[w][a * 28 + c] * svh[w][b * 28 + c];
        float sn = ss[w][tl] + HCONST * acc;
        swr[(size_t)i * 100 + tl] = sn;
        g_shist[(size_t)col * N_SAMP * 100 + (size_t)i * 100 + tl] = sn;
    }
    // x regen not needed after final layer (classify recomputes from s)
}

// ---------------- expand: trans[i][k][l] from s_hist -------------------------
__global__ __launch_bounds__(256) void expand_kernel(const float* __restrict__ X,
                                                     float* __restrict__ trans) {
    __shared__ float u[280], vh[280], sall[3300], US[1320], xs[3696];
    int i = blockIdx.x, t = threadIdx.x;
    const float* xb = X + (size_t)i * 840;
    for (int k = t; k < 280; k += 256) { u[k] = xb[k]; vh[k] = xb[560 + k]; }
    for (int k = t; k < 3300; k += 256) {
        int l = k / 100, j = k % 100;
        sall[k] = g_shist[(size_t)l * N_SAMP * 100 + (size_t)i * 100 + j];
    }
    __syncthreads();
    float* base = trans + (size_t)i * (DD * 33);
    for (int ch = 0; ch < 7; ch++) {
        int r0 = ch * 4;
        for (int k = t; k < 1320; k += 256) {
            int l = k / 40, rem = k % 40, rr = rem / 10, b = rem % 10;
            float acc = 0.f;
#pragma unroll
            for (int a = 0; a < 10; a++) acc += u[(r0 + rr) * 10 + a] * sall[l * 100 + a * 10 + b];
            US[k] = acc;
        }
        __syncthreads();
        for (int k = t; k < 3696; k += 256) {
            int l = k / 112, kk = k % 112, rr = kk / 28, c = kk % 28;
            float acc = 0.f;
#pragma unroll
            for (int b = 0; b < 10; b++) acc += US[l * 40 + rr * 10 + b] * vh[b * 28 + c];
            xs[k] = acc;
        }
        __syncthreads();
        for (int e = t; e < 3696; e += 256) {
            base[ch * 3696 + e] = xs[(e % 33) * 112 + e / 33];
        }
        __syncthreads();
    }
}

// ---------------- classify (s from ping-pong buf 1) --------------------------
__global__ __launch_bounds__(128) void classify_kernel(const float* __restrict__ X,
                                                       const float* __restrict__ Wc,
                                                       const float* __restrict__ bc,
                                                       float* __restrict__ pred,
                                                       float* __restrict__ cls) {
    __shared__ float u[280], vh[280], s[100], US[280], x[784], lgs[KCLS];
    int i = blockIdx.x, t = threadIdx.x;
    int w = t >> 5, lane = t & 31;
    const float* xb = X + (size_t)i * 840;
    const float* sfin = g_s2 + (size_t)1 * N_SAMP * 100;   // after update(32)
    for (int k = t; k < 280; k += 128) { u[k] = xb[k]; vh[k] = xb[560 + k]; }
    for (int k = t; k < 100; k += 128) s[k] = sfin[(size_t)i * 100 + k];
    __syncthreads();
    for (int k = t; k < 280; k += 128) {
        int r = k / 10, b = k % 10;
        float acc = 0.f;
#pragma unroll
        for (int a = 0; a < 10; a++) acc += u[r * 10 + a] * s[a * 10 + b];
        US[k] = acc;
    }
    __syncthreads();
    for (int k = t; k < 784; k += 128) {
        int r = k / 28, c = k % 28;
        float acc = 0.f;
#pragma unroll
        for (int b = 0; b < 10; b++) acc += US[r * 10 + b] * vh[b * 28 + c];
        x[k] = acc;
    }
    __syncthreads();
    for (int c = w; c < KCLS; c += 4) {
        const float* wr = Wc + (size_t)c * DD;
        float acc = 0.f;
#pragma unroll
        for (int it = 0; it < 25; it++) {
            int k = lane + 32 * it;
            if (k < 784) acc += x[k] * wr[k];
        }
#pragma unroll
        for (int o = 16; o; o >>= 1) acc += __shfl_down_sync(0xffffffffu, acc, o);
        if (lane == 0) lgs[c] = acc + bc[c];
    }
    __syncthreads();
    if (t == 0) {
        float mx = -1e30f;
#pragma unroll
        for (int c = 0; c < KCLS; c++) {
            cls[(size_t)i * KCLS + c] = lgs[c];
            if (lgs[c] > mx) mx = lgs[c];
        }
        float e[KCLS], ssum = 0.f;
#pragma unroll
        for (int c = 0; c < KCLS; c++) { e[c] = expf(lgs[c] - mx); ssum += e[c]; }
        float inv = 1.f / ssum;
#pragma unroll
        for (int c = 0; c < KCLS; c++) pred[(size_t)i * KCLS + c] = e[c] * inv;
    }
}

// ---------------- launcher ---------------------------------------------------
extern "C" void kernel_launch(void* const* d_in, const int* in_sizes, int n_in,
                              void* d_out, int out_size) {
    const float* X  = (const float*)d_in[0];
    const float* W0 = (const float*)d_in[1];
    const float* Ws = (const float*)d_in[2];
    const float* bs = (const float*)d_in[3];
    const float* Wc = (const float*)d_in[4];
    const float* bc = (const float*)d_in[5];
    float* out = (float*)d_out;
    float* pred  = out;
    float* cls   = out + (size_t)N_SAMP * KCLS;
    float* trans = out + (size_t)2 * N_SAMP * KCLS;

    static const __nv_bfloat16* wh_dev = nullptr;
    static bool configured = false;
    if (!configured) {
        void* p = nullptr;
        cudaGetSymbolAddress(&p, g_wh);
        wh_dev = (const __nv_bfloat16*)p;
        cudaFuncSetAttribute(layer_kernel, cudaFuncAttributeMaxDynamicSharedMemorySize,
                             GEMM_SMEM);
        configured = true;
    }

    {
        size_t total = (size_t)33 * DD * DD;
        int blocks = (int)((total / 4 + 255) / 256);
        wcvt_kernel<<<blocks, 256>>>(W0, Ws);
    }
    init_kernel<<<N_SAMP, 256>>>(X);

    dim3 ggrid(DD / GBN, N_SAMP / GBM);   // (7, 16)
    for (int col = 0; col < 33; col++) {
        const __nv_bfloat16* W = wh_dev + (size_t)col * DD * DD;
        const float* bias = (col > 0) ? (bs + (size_t)(col - 1) * DD) : nullptr;
        layer_kernel<<<ggrid, 256, GEMM_SMEM>>>(W, bias, col > 0 ? 1 : 0, col);
    }
    update_kernel<<<N_SAMP / 2, 256>>>(32);
    expand_kernel<<<N_SAMP, 256>>>(X, trans);
    classify_kernel<<<N_SAMP, 128>>>(X, Wc, bc, pred, cls);
}

// round 16
// speedup vs baseline: 3.7651x; 3.7651x over previous
#include <cuda_runtime.h>
#include <cuda_bf16.h>
#include <cstdint>
#include <math.h>

#define N_SAMP 2048
#define DD 784
#define KR 10
#define LAYERS 32
#define KCLS 10
#define HCONST 0.001f

__device__ float g_s[N_SAMP * 100];
__device__ float g_shist[33 * N_SAMP * 100];
__device__ __nv_bfloat16 g_xh[N_SAMP * DD];
__device__ __nv_bfloat16 g_zh[N_SAMP * DD];
__device__ __nv_bfloat16 g_wh[33 * DD * DD];
__device__ __nv_bfloat16 g_uvhh[N_SAMP * 560];

// ---------------- weights -> bf16 -------------------------------------------
__global__ void wcvt_kernel(const float* __restrict__ W0, const float* __restrict__ Ws) {
    size_t idx = ((size_t)blockIdx.x * blockDim.x + threadIdx.x) * 4;
    size_t total = (size_t)33 * DD * DD;
    if (idx >= total) return;
    size_t per = (size_t)DD * DD;
    const float* src = (idx < per) ? (W0 + idx) : (Ws + (idx - per));
    float4 v = *(const float4*)src;
    __nv_bfloat16 o[4] = {__float2bfloat16(v.x), __float2bfloat16(v.y),
                          __float2bfloat16(v.z), __float2bfloat16(v.w)};
    *(uint2*)(g_wh + idx) = *(uint2*)o;
}

// ---------------- init -------------------------------------------------------
__global__ void init_kernel(const float* __restrict__ X) {
    __shared__ float u[280], vh[280], s[100], US[280];
    int i = blockIdx.x, t = threadIdx.x;
    const float* xb = X + (size_t)i * 840;
    for (int k = t; k < 280; k += blockDim.x) {
        float uu = xb[k], vv = xb[560 + k];
        u[k] = uu; vh[k] = vv;
        g_uvhh[(size_t)i * 560 + k] = __float2bfloat16(uu);
        g_uvhh[(size_t)i * 560 + 280 + k] = __float2bfloat16(vv);
    }
    for (int k = t; k < 100; k += blockDim.x) { float v = xb[280 + k]; s[k] = v; g_s[i * 100 + k] = v; }
    __syncthreads();
    for (int k = t; k < 280; k += blockDim.x) {
        int r = k / 10, b = k % 10;
        float acc = 0.f;
#pragma unroll
        for (int a = 0; a < 10; a++) acc += u[r * 10 + a] * s[a * 10 + b];
        US[k] = acc;
    }
    __syncthreads();
    for (int k = t; k < DD; k += blockDim.x) {
        int r = k / 28, c = k % 28;
        float acc = 0.f;
#pragma unroll
        for (int b = 0; b < 10; b++) acc += US[r * 10 + b] * vh[b * 28 + c];
        g_xh[(size_t)i * DD + k] = __float2bfloat16(acc);
    }
}

// ---------------- GEMM: g_zh = relu(g_xh @ W^T + b), BM=128 BK=64, 3-stage --
#define GBM 128
#define GBN 112
#define GBK 64
#define SPAD 72
#define NIT 13
#define NST 3

__device__ __forceinline__ unsigned smem_u32(const void* p) {
    return (unsigned)__cvta_generic_to_shared(p);
}
__device__ __forceinline__ void cp16(unsigned dst, const void* src, int sz) {
    asm volatile("cp.async.cg.shared.global [%0], [%1], 16, %2;\n"
                 :: "r"(dst), "l"(src), "r"(sz));
}

__global__ __launch_bounds__(256) void gemm_tc_kernel(const __nv_bfloat16* __restrict__ W,
                                                      const float* __restrict__ bias,
                                                      int do_relu) {
    extern __shared__ char dsm[];
    __nv_bfloat16 (*As)[GBM][SPAD] = (__nv_bfloat16(*)[GBM][SPAD])dsm;
    __nv_bfloat16 (*Bs)[GBN][SPAD] =
        (__nv_bfloat16(*)[GBN][SPAD])(dsm + NST * GBM * SPAD * 2);
    int bm = blockIdx.y * GBM;
    int bn = blockIdx.x * GBN;
    int tid = threadIdx.x;
    int wid = tid >> 5, lane = tid & 31;
    int wm = wid & 3, wn = wid >> 2;      // warp tile 32 x 56
    int g = lane >> 2, tg = lane & 3;

    float acc[2][7][4] = {};

    auto load_stage = [&](int it, int buf) {
        int k0 = it * GBK;
#pragma unroll
        for (int ii = 0; ii < 4; ii++) {
            int task = tid + ii * 256;
            int row = task >> 3, cg = task & 7;
            int kk = k0 + 8 * cg;
            const __nv_bfloat16* src = g_xh + (size_t)(bm + row) * DD + kk;
            cp16(smem_u32(&As[buf][row][8 * cg]), src, (kk < DD) ? 16 : 0);
        }
#pragma unroll
        for (int ii = 0; ii < 4; ii++) {
            int task = tid + ii * 256;
            if (task < 896) {
                int row = task >> 3, cg = task & 7;
                int kk = k0 + 8 * cg;
                const __nv_bfloat16* src = W + (size_t)(bn + row) * DD + kk;
                cp16(smem_u32(&Bs[buf][row][8 * cg]), src, (kk < DD) ? 16 : 0);
            }
        }
        asm volatile("cp.async.commit_group;\n");
    };

    load_stage(0, 0);
    load_stage(1, 1);
    for (int it = 0; it < NIT; it++) {
        int buf = it % NST;
        if (it + 2 < NIT) {
            load_stage(it + 2, (it + 2) % NST);
            asm volatile("cp.async.wait_group 2;\n");
        } else if (it + 1 < NIT) {
            asm volatile("cp.async.wait_group 1;\n");
        } else {
            asm volatile("cp.async.wait_group 0;\n");
        }
        __syncthreads();
#pragma unroll
        for (int kh = 0; kh < 4; kh++) {
            int kk = 16 * kh;
            unsigned a[2][4];
#pragma unroll
            for (int mi = 0; mi < 2; mi++) {
                int r0 = wm * 32 + mi * 16 + g;
                a[mi][0] = *(const unsigned*)&As[buf][r0][kk + 2 * tg];
                a[mi][1] = *(const unsigned*)&As[buf][r0 + 8][kk + 2 * tg];
                a[mi][2] = *(const unsigned*)&As[buf][r0][kk + 2 * tg + 8];
                a[mi][3] = *(const unsigned*)&As[buf][r0 + 8][kk + 2 * tg + 8];
            }
#pragma unroll
            for (int j = 0; j < 7; j++) {
                int nr = wn * 56 + j * 8 + g;
                unsigned b0 = *(const unsigned*)&Bs[buf][nr][kk + 2 * tg];
                unsigned b1 = *(const unsigned*)&Bs[buf][nr][kk + 2 * tg + 8];
#pragma unroll
                for (int mi = 0; mi < 2; mi++) {
                    asm volatile(
                        "mma.sync.aligned.m16n8k16.row.col.f32.bf16.bf16.f32 "
                        "{%0,%1,%2,%3}, {%4,%5,%6,%7}, {%8,%9}, {%0,%1,%2,%3};"
                        : "+f"(acc[mi][j][0]), "+f"(acc[mi][j][1]),
                          "+f"(acc[mi][j][2]), "+f"(acc[mi][j][3])
                        : "r"(a[mi][0]), "r"(a[mi][1]), "r"(a[mi][2]), "r"(a[mi][3]),
                          "r"(b0), "r"(b1));
                }
            }
        }
        __syncthreads();
    }
    // epilogue: bias + relu -> bf16 packed
#pragma unroll
    for (int mi = 0; mi < 2; mi++) {
        int row0 = bm + wm * 32 + mi * 16 + g;
        int row1 = row0 + 8;
#pragma unroll
        for (int j = 0; j < 7; j++) {
            int col = bn + wn * 56 + j * 8 + 2 * tg;
            float b0 = bias ? bias[col] : 0.f;
            float b1 = bias ? bias[col + 1] : 0.f;
            float v00 = acc[mi][j][0] + b0, v01 = acc[mi][j][1] + b1;
            float v10 = acc[mi][j][2] + b0, v11 = acc[mi][j][3] + b1;
            if (do_relu) {
                v00 = fmaxf(v00, 0.f); v01 = fmaxf(v01, 0.f);
                v10 = fmaxf(v10, 0.f); v11 = fmaxf(v11, 0.f);
            }
            *(__nv_bfloat162*)(g_zh + (size_t)row0 * DD + col) =
                __float22bfloat162_rn(make_float2(v00, v01));
            *(__nv_bfloat162*)(g_zh + (size_t)row1 * DD + col) =
                __float22bfloat162_rn(make_float2(v10, v11));
        }
    }
}
#define GEMM_SMEM (NST * (GBM + GBN) * SPAD * 2)   // 103680

// ---------------- update: 128 threads/sample, 2 samples/block (R13) ---------
__global__ __launch_bounds__(256) void update_kernel(int col) {
    __shared__ float su[2][280], svh[2][280], sdY[2][784], sP[2][280], ss[2][104], sUS[2][280];
    int t = threadIdx.x;
    int w = t >> 7;
    int tl = t & 127;
    int i = blockIdx.x * 2 + w;
    const __nv_bfloat162* uvp = (const __nv_bfloat162*)(g_uvhh + (size_t)i * 560);
#pragma unroll
    for (int it = 0; it < 3; it++) {
        int k = tl + 128 * it;
        if (k < 280) {
            float2 p = __bfloat1622float2(uvp[k]);
            if (k < 140) { su[w][2 * k] = p.x; su[w][2 * k + 1] = p.y; }
            else { int k2 = k - 140; svh[w][2 * k2] = p.x; svh[w][2 * k2 + 1] = p.y; }
        }
    }
    const __nv_bfloat162* zsrc = (const __nv_bfloat162*)(g_zh + (size_t)i * DD);
#pragma unroll
    for (int it = 0; it < 4; it++) {
        int k = tl + 128 * it;
        if (k < 392) {
            float2 v = __bfloat1622float2(zsrc[k]);
            sdY[w][2 * k] = v.x; sdY[w][2 * k + 1] = v.y;
        }
    }
    if (tl < 100) ss[w][tl] = g_s[i * 100 + tl];
    __syncthreads();
#pragma unroll
    for (int it = 0; it < 3; it++) {
        int k = tl + 128 * it;
        if (k < 280) {
            int a = k / 28, c = k % 28;
            float acc = 0.f;
#pragma unroll
            for (int r = 0; r < 28; r++) acc += su[w][r * 10 + a] * sdY[w][r * 28 + c];
            sP[w][k] = acc;
        }
    }
    __syncthreads();
    if (tl < 100) {
        int a = tl / 10, b = tl % 10;
        float acc = 0.f;
#pragma unroll
        for (int c = 0; c < 28; c++) acc += sP[w][a * 28 + c] * svh[w][b * 28 + c];
        float sn = ss[w][tl] + HCONST * acc;
        ss[w][tl] = sn;
        g_s[i * 100 + tl] = sn;
        g_shist[(size_t)col * N_SAMP * 100 + (size_t)i * 100 + tl] = sn;
    }
    __syncthreads();
#pragma unroll
    for (int it = 0; it < 3; it++) {
        int k = tl + 128 * it;
        if (k < 280) {
            int r = k / 10, b = k % 10;
            float acc = 0.f;
#pragma unroll
            for (int a = 0; a < 10; a++) acc += su[w][r * 10 + a] * ss[w][a * 10 + b];
            sUS[w][k] = acc;
        }
    }
    __syncthreads();
    __nv_bfloat162* xdst = (__nv_bfloat162*)(g_xh + (size_t)i * DD);
#pragma unroll
    for (int it = 0; it < 4; it++) {
        int p = tl + 128 * it;
        if (p < 392) {
            int r = p / 14, cc = (p % 14) * 2;
            float a0 = 0.f, a1 = 0.f;
#pragma unroll
            for (int b = 0; b < 10; b++) {
                float us = sUS[w][r * 10 + b];
                a0 += us * svh[w][b * 28 + cc];
                a1 += us * svh[w][b * 28 + cc + 1];
            }
            xdst[p] = __float22bfloat162_rn(make_float2(a0, a1));
        }
    }
}

// ---------------- expand: trans[i][k][l] from s_hist -------------------------
__global__ __launch_bounds__(256) void expand_kernel(const float* __restrict__ X,
                                                     float* __restrict__ trans) {
    __shared__ float u[280], vh[280], sall[3300], US[1320], xs[3696];
    int i = blockIdx.x, t = threadIdx.x;
    const float* xb = X + (size_t)i * 840;
    for (int k = t; k < 280; k += 256) { u[k] = xb[k]; vh[k] = xb[560 + k]; }
    for (int k = t; k < 3300; k += 256) {
        int l = k / 100, j = k % 100;
        sall[k] = g_shist[(size_t)l * N_SAMP * 100 + (size_t)i * 100 + j];
    }
    __syncthreads();
    float* base = trans + (size_t)i * (DD * 33);
    for (int ch = 0; ch < 7; ch++) {
        int r0 = ch * 4;
        for (int k = t; k < 1320; k += 256) {
            int l = k / 40, rem = k % 40, rr = rem / 10, b = rem % 10;
            float acc = 0.f;
#pragma unroll
            for (int a = 0; a < 10; a++) acc += u[(r0 + rr) * 10 + a] * sall[l * 100 + a * 10 + b];
            US[k] = acc;
        }
        __syncthreads();
        for (int k = t; k < 3696; k += 256) {
            int l = k / 112, kk = k % 112, rr = kk / 28, c = kk % 28;
            float acc = 0.f;
#pragma unroll
            for (int b = 0; b < 10; b++) acc += US[l * 40 + rr * 10 + b] * vh[b * 28 + c];
            xs[k] = acc;
        }
        __syncthreads();
        for (int e = t; e < 3696; e += 256) {
            base[ch * 3696 + e] = xs[(e % 33) * 112 + e / 33];
        }
        __syncthreads();
    }
}

// ---------------- classify ---------------------------------------------------
__global__ __launch_bounds__(128) void classify_kernel(const float* __restrict__ X,
                                                       const float* __restrict__ Wc,
                                                       const float* __restrict__ bc,
                                                       float* __restrict__ pred,
                                                       float* __restrict__ cls) {
    __shared__ float u[280], vh[280], s[100], US[280], x[784], lgs[KCLS];
    int i = blockIdx.x, t = threadIdx.x;
    int w = t >> 5, lane = t & 31;
    const float* xb = X + (size_t)i * 840;
    for (int k = t; k < 280; k += 128) { u[k] = xb[k]; vh[k] = xb[560 + k]; }
    for (int k = t; k < 100; k += 128) s[k] = g_s[i * 100 + k];
    __syncthreads();
    for (int k = t; k < 280; k += 128) {
        int r = k / 10, b = k % 10;
        float acc = 0.f;
#pragma unroll
        for (int a = 0; a < 10; a++) acc += u[r * 10 + a] * s[a * 10 + b];
        US[k] = acc;
    }
    __syncthreads();
    for (int k = t; k < 784; k += 128) {
        int r = k / 28, c = k % 28;
        float acc = 0.f;
#pragma unroll
        for (int b = 0; b < 10; b++) acc += US[r * 10 + b] * vh[b * 28 + c];
        x[k] = acc;
    }
    __syncthreads();
    for (int c = w; c < KCLS; c += 4) {
        const float* wr = Wc + (size_t)c * DD;
        float acc = 0.f;
#pragma unroll
        for (int it = 0; it < 25; it++) {
            int k = lane + 32 * it;
            if (k < 784) acc += x[k] * wr[k];
        }
#pragma unroll
        for (int o = 16; o; o >>= 1) acc += __shfl_down_sync(0xffffffffu, acc, o);
        if (lane == 0) lgs[c] = acc + bc[c];
    }
    __syncthreads();
    if (t == 0) {
        float mx = -1e30f;
#pragma unroll
        for (int c = 0; c < KCLS; c++) {
            cls[(size_t)i * KCLS + c] = lgs[c];
            if (lgs[c] > mx) mx = lgs[c];
        }
        float e[KCLS], ssum = 0.f;
#pragma unroll
        for (int c = 0; c < KCLS; c++) { e[c] = expf(lgs[c] - mx); ssum += e[c]; }
        float inv = 1.f / ssum;
#pragma unroll
        for (int c = 0; c < KCLS; c++) pred[(size_t)i * KCLS + c] = e[c] * inv;
    }
}

// ---------------- launcher ---------------------------------------------------
extern "C" void kernel_launch(void* const* d_in, const int* in_sizes, int n_in,
                              void* d_out, int out_size) {
    const float* X  = (const float*)d_in[0];
    const float* W0 = (const float*)d_in[1];
    const float* Ws = (const float*)d_in[2];
    const float* bs = (const float*)d_in[3];
    const float* Wc = (const float*)d_in[4];
    const float* bc = (const float*)d_in[5];
    float* out = (float*)d_out;
    float* pred  = out;
    float* cls   = out + (size_t)N_SAMP * KCLS;
    float* trans = out + (size_t)2 * N_SAMP * KCLS;

    static const __nv_bfloat16* wh_dev = nullptr;
    static bool configured = false;
    if (!configured) {
        void* p = nullptr;
        cudaGetSymbolAddress(&p, g_wh);
        wh_dev = (const __nv_bfloat16*)p;
        cudaFuncSetAttribute(gemm_tc_kernel, cudaFuncAttributeMaxDynamicSharedMemorySize,
                             GEMM_SMEM);
        configured = true;
    }

    {
        size_t total = (size_t)33 * DD * DD;
        int blocks = (int)((total / 4 + 255) / 256);
        wcvt_kernel<<<blocks, 256>>>(W0, Ws);
    }
    init_kernel<<<N_SAMP, 256>>>(X);

    dim3 ggrid(DD / GBN, N_SAMP / GBM);   // (7, 16)
    for (int col = 0; col < 33; col++) {
        const __nv_bfloat16* W = wh_dev + (size_t)col * DD * DD;
        const float* bias = (col > 0) ? (bs + (size_t)(col - 1) * DD) : nullptr;
        gemm_tc_kernel<<<ggrid, 256, GEMM_SMEM>>>(W, bias, col > 0 ? 1 : 0);
        update_kernel<<<N_SAMP / 2, 256>>>(col);
    }
    expand_kernel<<<N_SAMP, 256>>>(X, trans);
    classify_kernel<<<N_SAMP, 128>>>(X, Wc, bc, pred, cls);
}

// round 17
// speedup vs baseline: 3.9056x; 1.0373x over previous
#include <cuda_runtime.h>
#include <cuda_bf16.h>
#include <cstdint>
#include <math.h>

#define N_SAMP 2048
#define DD 784
#define KR 10
#define LAYERS 32
#define KCLS 10
#define HCONST 0.001f

__device__ float g_s[N_SAMP * 100];
__device__ float g_shist[33 * N_SAMP * 100];
__device__ __nv_bfloat16 g_xh[N_SAMP * DD];
__device__ __nv_bfloat16 g_zh[N_SAMP * DD];
__device__ __nv_bfloat16 g_wh[33 * DD * DD];
__device__ __nv_bfloat16 g_uvhh[N_SAMP * 560];

// ---------------- weights -> bf16 -------------------------------------------
__global__ void wcvt_kernel(const float* __restrict__ W0, const float* __restrict__ Ws) {
    size_t idx = ((size_t)blockIdx.x * blockDim.x + threadIdx.x) * 4;
    size_t total = (size_t)33 * DD * DD;
    if (idx >= total) return;
    size_t per = (size_t)DD * DD;
    const float* src = (idx < per) ? (W0 + idx) : (Ws + (idx - per));
    float4 v = *(const float4*)src;
    __nv_bfloat16 o[4] = {__float2bfloat16(v.x), __float2bfloat16(v.y),
                          __float2bfloat16(v.z), __float2bfloat16(v.w)};
    *(uint2*)(g_wh + idx) = *(uint2*)o;
}

// ---------------- init -------------------------------------------------------
__global__ void init_kernel(const float* __restrict__ X) {
    __shared__ float u[280], vh[280], s[100], US[280];
    int i = blockIdx.x, t = threadIdx.x;
    const float* xb = X + (size_t)i * 840;
    for (int k = t; k < 280; k += blockDim.x) {
        float uu = xb[k], vv = xb[560 + k];
        u[k] = uu; vh[k] = vv;
        g_uvhh[(size_t)i * 560 + k] = __float2bfloat16(uu);
        g_uvhh[(size_t)i * 560 + 280 + k] = __float2bfloat16(vv);
    }
    for (int k = t; k < 100; k += blockDim.x) { float v = xb[280 + k]; s[k] = v; g_s[i * 100 + k] = v; }
    __syncthreads();
    for (int k = t; k < 280; k += blockDim.x) {
        int r = k / 10, b = k % 10;
        float acc = 0.f;
#pragma unroll
        for (int a = 0; a < 10; a++) acc += u[r * 10 + a] * s[a * 10 + b];
        US[k] = acc;
    }
    __syncthreads();
    for (int k = t; k < DD; k += blockDim.x) {
        int r = k / 28, c = k % 28;
        float acc = 0.f;
#pragma unroll
        for (int b = 0; b < 10; b++) acc += US[r * 10 + b] * vh[b * 28 + c];
        g_xh[(size_t)i * DD + k] = __float2bfloat16(acc);
    }
}

// ---------------- GEMM: g_zh = relu(g_xh @ W^T + b), BM=128 BK=112 ----------
// 784 = 7 x 112: exactly 7 k-iterations, zero tail waste, 14 barriers.
#define GBM 128
#define GBN 112
#define GBK 112
#define SPAD 120          // 240-byte rows: 16B aligned, conflict-free fragments
#define NIT 7
#define NCHK 14           // 112 bf16 = 14 x 16B chunks per row
#define GEMM_SMEM (2 * (GBM + GBN) * SPAD * 2)   // 115200

__device__ __forceinline__ unsigned smem_u32(const void* p) {
    return (unsigned)__cvta_generic_to_shared(p);
}
__device__ __forceinline__ void cp16(unsigned dst, const void* src) {
    asm volatile("cp.async.cg.shared.global [%0], [%1], 16;\n"
                 :: "r"(dst), "l"(src));
}

__global__ __launch_bounds__(256) void gemm_tc_kernel(const __nv_bfloat16* __restrict__ W,
                                                      const float* __restrict__ bias,
                                                      int do_relu) {
    extern __shared__ char dsm[];
    __nv_bfloat16 (*As)[GBM][SPAD] = (__nv_bfloat16(*)[GBM][SPAD])dsm;
    __nv_bfloat16 (*Bs)[GBN][SPAD] =
        (__nv_bfloat16(*)[GBN][SPAD])(dsm + 2 * GBM * SPAD * 2);
    int bm = blockIdx.y * GBM;
    int bn = blockIdx.x * GBN;
    int tid = threadIdx.x;
    int wid = tid >> 5, lane = tid & 31;
    int wm = wid & 3, wn = wid >> 2;      // warp tile 32 x 56
    int g = lane >> 2, tg = lane & 3;

    float acc[2][7][4] = {};

    // A: 128 rows x 14 chunks = 1792 tasks; B: 112 x 14 = 1568; total 3360
    auto load_stage = [&](int it, int buf) {
        int k0 = it * GBK;
#pragma unroll
        for (int ii = 0; ii < 14; ii++) {
            int task = tid + ii * 256;
            if (task < 1792) {
                int row = task / NCHK, cg = task % NCHK;
                const __nv_bfloat16* src = g_xh + (size_t)(bm + row) * DD + k0 + 8 * cg;
                cp16(smem_u32(&As[buf][row][8 * cg]), src);
            } else if (task < 3360) {
                int t2 = task - 1792;
                int row = t2 / NCHK, cg = t2 % NCHK;
                const __nv_bfloat16* src = W + (size_t)(bn + row) * DD + k0 + 8 * cg;
                cp16(smem_u32(&Bs[buf][row][8 * cg]), src);
            }
        }
        asm volatile("cp.async.commit_group;\n");
    };

    load_stage(0, 0);
    for (int it = 0; it < NIT; it++) {
        int buf = it & 1;
        if (it + 1 < NIT) {
            load_stage(it + 1, buf ^ 1);
            asm volatile("cp.async.wait_group 1;\n");
        } else {
            asm volatile("cp.async.wait_group 0;\n");
        }
        __syncthreads();
#pragma unroll
        for (int kh = 0; kh < 7; kh++) {
            int kk = 16 * kh;
            unsigned a[2][4];
#pragma unroll
            for (int mi = 0; mi < 2; mi++) {
                int r0 = wm * 32 + mi * 16 + g;
                a[mi][0] = *(const unsigned*)&As[buf][r0][kk + 2 * tg];
                a[mi][1] = *(const unsigned*)&As[buf][r0 + 8][kk + 2 * tg];
                a[mi][2] = *(const unsigned*)&As[buf][r0][kk + 2 * tg + 8];
                a[mi][3] = *(const unsigned*)&As[buf][r0 + 8][kk + 2 * tg + 8];
            }
#pragma unroll
            for (int j = 0; j < 7; j++) {
                int nr = wn * 56 + j * 8 + g;
                unsigned b0 = *(const unsigned*)&Bs[buf][nr][kk + 2 * tg];
                unsigned b1 = *(const unsigned*)&Bs[buf][nr][kk + 2 * tg + 8];
#pragma unroll
                for (int mi = 0; mi < 2; mi++) {
                    asm volatile(
                        "mma.sync.aligned.m16n8k16.row.col.f32.bf16.bf16.f32 "
                        "{%0,%1,%2,%3}, {%4,%5,%6,%7}, {%8,%9}, {%0,%1,%2,%3};"
                        : "+f"(acc[mi][j][0]), "+f"(acc[mi][j][1]),
                          "+f"(acc[mi][j][2]), "+f"(acc[mi][j][3])
                        : "r"(a[mi][0]), "r"(a[mi][1]), "r"(a[mi][2]), "r"(a[mi][3]),
                          "r"(b0), "r"(b1));
                }
            }
        }
        __syncthreads();
    }
    // epilogue: bias + relu -> bf16 packed
#pragma unroll
    for (int mi = 0; mi < 2; mi++) {
        int row0 = bm + wm * 32 + mi * 16 + g;
        int row1 = row0 + 8;
#pragma unroll
        for (int j = 0; j < 7; j++) {
            int col = bn + wn * 56 + j * 8 + 2 * tg;
            float b0 = bias ? bias[col] : 0.f;
            float b1 = bias ? bias[col + 1] : 0.f;
            float v00 = acc[mi][j][0] + b0, v01 = acc[mi][j][1] + b1;
            float v10 = acc[mi][j][2] + b0, v11 = acc[mi][j][3] + b1;
            if (do_relu) {
                v00 = fmaxf(v00, 0.f); v01 = fmaxf(v01, 0.f);
                v10 = fmaxf(v10, 0.f); v11 = fmaxf(v11, 0.f);
            }
            *(__nv_bfloat162*)(g_zh + (size_t)row0 * DD + col) =
                __float22bfloat162_rn(make_float2(v00, v01));
            *(__nv_bfloat162*)(g_zh + (size_t)row1 * DD + col) =
                __float22bfloat162_rn(make_float2(v10, v11));
        }
    }
}

// ---------------- update: 128 threads/sample, 2 samples/block (R13) ---------
__global__ __launch_bounds__(256) void update_kernel(int col) {
    __shared__ float su[2][280], svh[2][280], sdY[2][784], sP[2][280], ss[2][104], sUS[2][280];
    int t = threadIdx.x;
    int w = t >> 7;
    int tl = t & 127;
    int i = blockIdx.x * 2 + w;
    const __nv_bfloat162* uvp = (const __nv_bfloat162*)(g_uvhh + (size_t)i * 560);
#pragma unroll
    for (int it = 0; it < 3; it++) {
        int k = tl + 128 * it;
        if (k < 280) {
            float2 p = __bfloat1622float2(uvp[k]);
            if (k < 140) { su[w][2 * k] = p.x; su[w][2 * k + 1] = p.y; }
            else { int k2 = k - 140; svh[w][2 * k2] = p.x; svh[w][2 * k2 + 1] = p.y; }
        }
    }
    const __nv_bfloat162* zsrc = (const __nv_bfloat162*)(g_zh + (size_t)i * DD);
#pragma unroll
    for (int it = 0; it < 4; it++) {
        int k = tl + 128 * it;
        if (k < 392) {
            float2 v = __bfloat1622float2(zsrc[k]);
            sdY[w][2 * k] = v.x; sdY[w][2 * k + 1] = v.y;
        }
    }
    if (tl < 100) ss[w][tl] = g_s[i * 100 + tl];
    __syncthreads();
#pragma unroll
    for (int it = 0; it < 3; it++) {
        int k = tl + 128 * it;
        if (k < 280) {
            int a = k / 28, c = k % 28;
            float acc = 0.f;
#pragma unroll
            for (int r = 0; r < 28; r++) acc += su[w][r * 10 + a] * sdY[w][r * 28 + c];
            sP[w][k] = acc;
        }
    }
    __syncthreads();
    if (tl < 100) {
        int a = tl / 10, b = tl % 10;
        float acc = 0.f;
#pragma unroll
        for (int c = 0; c < 28; c++) acc += sP[w][a * 28 + c] * svh[w][b * 28 + c];
        float sn = ss[w][tl] + HCONST * acc;
        ss[w][tl] = sn;
        g_s[i * 100 + tl] = sn;
        g_shist[(size_t)col * N_SAMP * 100 + (size_t)i * 100 + tl] = sn;
    }
    __syncthreads();
#pragma unroll
    for (int it = 0; it < 3; it++) {
        int k = tl + 128 * it;
        if (k < 280) {
            int r = k / 10, b = k % 10;
            float acc = 0.f;
#pragma unroll
            for (int a = 0; a < 10; a++) acc += su[w][r * 10 + a] * ss[w][a * 10 + b];
            sUS[w][k] = acc;
        }
    }
    __syncthreads();
    __nv_bfloat162* xdst = (__nv_bfloat162*)(g_xh + (size_t)i * DD);
#pragma unroll
    for (int it = 0; it < 4; it++) {
        int p = tl + 128 * it;
        if (p < 392) {
            int r = p / 14, cc = (p % 14) * 2;
            float a0 = 0.f, a1 = 0.f;
#pragma unroll
            for (int b = 0; b < 10; b++) {
                float us = sUS[w][r * 10 + b];
                a0 += us * svh[w][b * 28 + cc];
                a1 += us * svh[w][b * 28 + cc + 1];
            }
            xdst[p] = __float22bfloat162_rn(make_float2(a0, a1));
        }
    }
}

// ---------------- expand: trans[i][k][l] from s_hist -------------------------
__global__ __launch_bounds__(256) void expand_kernel(const float* __restrict__ X,
                                                     float* __restrict__ trans) {
    __shared__ float u[280], vh[280], sall[3300], US[1320], xs[3696];
    int i = blockIdx.x, t = threadIdx.x;
    const float* xb = X + (size_t)i * 840;
    for (int k = t; k < 280; k += 256) { u[k] = xb[k]; vh[k] = xb[560 + k]; }
    for (int k = t; k < 3300; k += 256) {
        int l = k / 100, j = k % 100;
        sall[k] = g_shist[(size_t)l * N_SAMP * 100 + (size_t)i * 100 + j];
    }
    __syncthreads();
    float* base = trans + (size_t)i * (DD * 33);
    for (int ch = 0; ch < 7; ch++) {
        int r0 = ch * 4;
        for (int k = t; k < 1320; k += 256) {
            int l = k / 40, rem = k % 40, rr = rem / 10, b = rem % 10;
            float acc = 0.f;
#pragma unroll
            for (int a = 0; a < 10; a++) acc += u[(r0 + rr) * 10 + a] * sall[l * 100 + a * 10 + b];
            US[k] = acc;
        }
        __syncthreads();
        for (int k = t; k < 3696; k += 256) {
            int l = k / 112, kk = k % 112, rr = kk / 28, c = kk % 28;
            float acc = 0.f;
#pragma unroll
            for (int b = 0; b < 10; b++) acc += US[l * 40 + rr * 10 + b] * vh[b * 28 + c];
            xs[k] = acc;
        }
        __syncthreads();
        for (int e = t; e < 3696; e += 256) {
            base[ch * 3696 + e] = xs[(e % 33) * 112 + e / 33];
        }
        __syncthreads();
    }
}

// ---------------- classify ---------------------------------------------------
__global__ __launch_bounds__(128) void classify_kernel(const float* __restrict__ X,
                                                       const float* __restrict__ Wc,
                                                       const float* __restrict__ bc,
                                                       float* __restrict__ pred,
                                                       float* __restrict__ cls) {
    __shared__ float u[280], vh[280], s[100], US[280], x[784], lgs[KCLS];
    int i = blockIdx.x, t = threadIdx.x;
    int w = t >> 5, lane = t & 31;
    const float* xb = X + (size_t)i * 840;
    for (int k = t; k < 280; k += 128) { u[k] = xb[k]; vh[k] = xb[560 + k]; }
    for (int k = t; k < 100; k += 128) s[k] = g_s[i * 100 + k];
    __syncthreads();
    for (int k = t; k < 280; k += 128) {
        int r = k / 10, b = k % 10;
        float acc = 0.f;
#pragma unroll
        for (int a = 0; a < 10; a++) acc += u[r * 10 + a] * s[a * 10 + b];
        US[k] = acc;
    }
    __syncthreads();
    for (int k = t; k < 784; k += 128) {
        int r = k / 28, c = k % 28;
        float acc = 0.f;
#pragma unroll
        for (int b = 0; b < 10; b++) acc += US[r * 10 + b] * vh[b * 28 + c];
        x[k] = acc;
    }
    __syncthreads();
    for (int c = w; c < KCLS; c += 4) {
        const float* wr = Wc + (size_t)c * DD;
        float acc = 0.f;
#pragma unroll
        for (int it = 0; it < 25; it++) {
            int k = lane + 32 * it;
            if (k < 784) acc += x[k] * wr[k];
        }
#pragma unroll
        for (int o = 16; o; o >>= 1) acc += __shfl_down_sync(0xffffffffu, acc, o);
        if (lane == 0) lgs[c] = acc + bc[c];
    }
    __syncthreads();
    if (t == 0) {
        float mx = -1e30f;
#pragma unroll
        for (int c = 0; c < KCLS; c++) {
            cls[(size_t)i * KCLS + c] = lgs[c];
            if (lgs[c] > mx) mx = lgs[c];
        }
        float e[KCLS], ssum = 0.f;
#pragma unroll
        for (int c = 0; c < KCLS; c++) { e[c] = expf(lgs[c] - mx); ssum += e[c]; }
        float inv = 1.f / ssum;
#pragma unroll
        for (int c = 0; c < KCLS; c++) pred[(size_t)i * KCLS + c] = e[c] * inv;
    }
}

// ---------------- launcher ---------------------------------------------------
extern "C" void kernel_launch(void* const* d_in, const int* in_sizes, int n_in,
                              void* d_out, int out_size) {
    const float* X  = (const float*)d_in[0];
    const float* W0 = (const float*)d_in[1];
    const float* Ws = (const float*)d_in[2];
    const float* bs = (const float*)d_in[3];
    const float* Wc = (const float*)d_in[4];
    const float* bc = (const float*)d_in[5];
    float* out = (float*)d_out;
    float* pred  = out;
    float* cls   = out + (size_t)N_SAMP * KCLS;
    float* trans = out + (size_t)2 * N_SAMP * KCLS;

    static const __nv_bfloat16* wh_dev = nullptr;
    static bool configured = false;
    if (!configured) {
        void* p = nullptr;
        cudaGetSymbolAddress(&p, g_wh);
        wh_dev = (const __nv_bfloat16*)p;
        cudaFuncSetAttribute(gemm_tc_kernel, cudaFuncAttributeMaxDynamicSharedMemorySize,
                             GEMM_SMEM);
        configured = true;
    }

    {
        size_t total = (size_t)33 * DD * DD;
        int blocks = (int)((total / 4 + 255) / 256);
        wcvt_kernel<<<blocks, 256>>>(W0, Ws);
    }
    init_kernel<<<N_SAMP, 256>>>(X);

    dim3 ggrid(DD / GBN, N_SAMP / GBM);   // (7, 16)
    for (int col = 0; col < 33; col++) {
        const __nv_bfloat16* W = wh_dev + (size_t)col * DD * DD;
        const float* bias = (col > 0) ? (bs + (size_t)(col - 1) * DD) : nullptr;
        gemm_tc_kernel<<<ggrid, 256, GEMM_SMEM>>>(W, bias, col > 0 ? 1 : 0);
        update_kernel<<<N_SAMP / 2, 256>>>(col);
    }
    expand_kernel<<<N_SAMP, 256>>>(X, trans);
    classify_kernel<<<N_SAMP, 128>>>(X, Wc, bc, pred, cls);
}